// round 2
// baseline (speedup 1.0000x reference)
#include <cuda_runtime.h>
#include <cuda_bf16.h>

// Problem constants (fixed by the dataset): B=8, T=128, U=64, V=512
#define Bc  8
#define Tc  128
#define Uc  64
#define U1c 65
#define Vc  512
#define NEGV -1e30f

// ------------------------------------------------------------------
// Scratch (device globals; no allocation allowed)
// ------------------------------------------------------------------
__device__ float g_expT[Bc * Tc * Vc];    // exp(trans - rowmax)
__device__ float g_expP[Bc * U1c * Vc];   // exp(pred  - rowmax)
__device__ float g_Mt[Bc * Tc];
__device__ float g_tb0[Bc * Tc];          // trans[b,t,0]
__device__ float g_Mu[Bc * U1c];
__device__ float g_pb0[Bc * U1c];         // pred[b,u,0]
__device__ float g_plab[Bc * Uc];         // pred[b,u,labels[b,u]]
__device__ float g_blank[Bc * Tc * U1c];  // blank log-prob per cell
__device__ float g_lab[Bc * Tc * Uc];     // label log-prob per cell (masked)
__device__ float g_cost[Bc];

// ------------------------------------------------------------------
// K1: per-row max + exp(x - max), plus scalar gathers
// blocks [0, B*T)        -> trans rows
// blocks [B*T, B*T+B*U1) -> pred rows
// ------------------------------------------------------------------
__global__ void k_prep(const float* __restrict__ trans,
                       const float* __restrict__ pred,
                       const int*   __restrict__ labels)
{
    int blk = blockIdx.x;
    bool isT = (blk < Bc * Tc);
    int idx = isT ? blk : (blk - Bc * Tc);
    const float* row = isT ? (trans + (size_t)idx * Vc) : (pred + (size_t)idx * Vc);
    float*      erow = isT ? (g_expT + (size_t)idx * Vc) : (g_expP + (size_t)idx * Vc);

    int tid = threadIdx.x;                 // 128 threads, 4 floats each
    float4 v = ((const float4*)row)[tid];

    float m = fmaxf(fmaxf(v.x, v.y), fmaxf(v.z, v.w));
#pragma unroll
    for (int o = 16; o; o >>= 1)
        m = fmaxf(m, __shfl_xor_sync(0xffffffffu, m, o));

    __shared__ float sm[4];
    if ((tid & 31) == 0) sm[tid >> 5] = m;
    __syncthreads();
    m = fmaxf(fmaxf(sm[0], sm[1]), fmaxf(sm[2], sm[3]));

    float4 e;
    e.x = __expf(v.x - m);
    e.y = __expf(v.y - m);
    e.z = __expf(v.z - m);
    e.w = __expf(v.w - m);
    ((float4*)erow)[tid] = e;

    if (tid == 0) {
        if (isT) {
            g_Mt[idx]  = m;
            g_tb0[idx] = v.x;              // v.x of tid 0 == row[0]
        } else {
            g_Mu[idx]  = m;
            g_pb0[idx] = v.x;
            int b = idx / U1c, u = idx % U1c;
            if (u < Uc) {
                int l = labels[b * Uc + u];
                g_plab[b * Uc + u] = row[l];
            }
        }
    }
}

// ------------------------------------------------------------------
// K2: joint dots + log-probs.
// Block handles (b, 4 consecutive t rows), 128 threads (4 floats/thread).
// Per u: dot(expT_row_j, expP_row_u) for j=0..3 via interleaved warp
// reductions; 4-thread tail emits blank_lp / lab_lp.
// ------------------------------------------------------------------
__global__ void k_joint(const float* __restrict__ trans,
                        const int*   __restrict__ labels,
                        const int*   __restrict__ label_lens)
{
    int b  = blockIdx.y;
    int t0 = blockIdx.x * 4;
    int tid = threadIdx.x, lane = tid & 31, w = tid >> 5;

    const float* eT = g_expT + ((size_t)(b * Tc + t0)) * Vc;
    float4 a0 = ((const float4*)(eT + 0 * Vc))[tid];
    float4 a1 = ((const float4*)(eT + 1 * Vc))[tid];
    float4 a2 = ((const float4*)(eT + 2 * Vc))[tid];
    float4 a3 = ((const float4*)(eT + 3 * Vc))[tid];

    __shared__ float part[2][4][4];        // [parity][warp][t-row]
    __shared__ float sMt[4], stb0[4];
    __shared__ int   sLL;
    if (tid < 4) {
        sMt[tid]  = g_Mt[b * Tc + t0 + tid];
        stb0[tid] = g_tb0[b * Tc + t0 + tid];
        if (tid == 0) sLL = label_lens[b];
    }
    __syncthreads();

    const float4* P = (const float4*)(g_expP + (size_t)b * U1c * Vc);
    float4 p = P[tid];                     // prefetch u = 0

    for (int u = 0; u < U1c; ++u) {
        float4 pc = p;
        if (u + 1 < U1c) p = P[(u + 1) * (Vc / 4) + tid];

        float s0 = a0.x * pc.x + a0.y * pc.y + a0.z * pc.z + a0.w * pc.w;
        float s1 = a1.x * pc.x + a1.y * pc.y + a1.z * pc.z + a1.w * pc.w;
        float s2 = a2.x * pc.x + a2.y * pc.y + a2.z * pc.z + a2.w * pc.w;
        float s3 = a3.x * pc.x + a3.y * pc.y + a3.z * pc.z + a3.w * pc.w;

#pragma unroll
        for (int o = 16; o; o >>= 1) {
            s0 += __shfl_xor_sync(0xffffffffu, s0, o);
            s1 += __shfl_xor_sync(0xffffffffu, s1, o);
            s2 += __shfl_xor_sync(0xffffffffu, s2, o);
            s3 += __shfl_xor_sync(0xffffffffu, s3, o);
        }
        int par = u & 1;
        if (lane == 0) {
            part[par][w][0] = s0;
            part[par][w][1] = s1;
            part[par][w][2] = s2;
            part[par][w][3] = s3;
        }
        __syncthreads();
        if (tid < 4) {
            float S = part[par][0][tid] + part[par][1][tid]
                    + part[par][2][tid] + part[par][3][tid];
            int t = t0 + tid;
            float logZ = sMt[tid] + g_Mu[b * U1c + u] + __logf(S);
            g_blank[((size_t)(b * Tc + t)) * U1c + u]
                = stb0[tid] + g_pb0[b * U1c + u] - logZ;
            if (u < Uc) {
                float lv;
                if (u < sLL) {
                    int l = labels[b * Uc + u];
                    lv = trans[((size_t)(b * Tc + t)) * Vc + l]
                       + g_plab[b * Uc + u] - logZ;
                } else {
                    lv = NEGV;
                }
                g_lab[((size_t)(b * Tc + t)) * Uc + u] = lv;
            }
        }
    }
}

// ------------------------------------------------------------------
// K3: alpha DP, anti-diagonal wavefront. One block per batch element,
// thread u owns lattice column u. 192 diagonal steps, 1 bar/step.
// alpha[t][u] = logaddexp(alpha[t-1][u] + blank[t-1][u],
//                         alpha[t][u-1] + lab[t][u-1])
// ------------------------------------------------------------------
__global__ void k_dp(const int* __restrict__ act_lens,
                     const int* __restrict__ label_lens)
{
    int b = blockIdx.x;
    int u = threadIdx.x;                   // 96 threads, active u <= 64
    __shared__ float diag[2][U1c];

    int tlen = act_lens[b];
    int ulen = label_lens[b];
    const float* BL = g_blank + (size_t)b * Tc * U1c;
    const float* LB = g_lab   + (size_t)b * Tc * Uc;

    float myPrev = 0.0f;

    for (int s = 0; s <= (Tc - 1) + Uc; ++s) {
        int cur = s & 1, prv = cur ^ 1;
        bool active = (u <= Uc) && (u <= s) && ((s - u) <= Tc - 1);
        if (active) {
            int t = s - u;
            float val;
            if (t == 0) {
                val = (u == 0) ? 0.0f
                               : diag[prv][u - 1] + LB[(size_t)0 * Uc + (u - 1)];
            } else if (u == 0) {
                val = myPrev + BL[(size_t)(t - 1) * U1c];
            } else {
                float A  = myPrev          + BL[(size_t)(t - 1) * U1c + u];
                float Bv = diag[prv][u - 1] + LB[(size_t)t * Uc + (u - 1)];
                float m  = fmaxf(A, Bv);
                val = m + __logf(1.0f + __expf(-fabsf(A - Bv)));
            }
            diag[cur][u] = val;
            myPrev = val;
            if (t == tlen - 1 && u == ulen)
                g_cost[b] = -(val + BL[(size_t)t * U1c + u]);
        }
        __syncthreads();
    }
}

// ------------------------------------------------------------------
// K4: sum per-batch costs into the single output element
// ------------------------------------------------------------------
__global__ void k_final(float* __restrict__ out)
{
    float c = (threadIdx.x < Bc) ? g_cost[threadIdx.x] : 0.0f;
#pragma unroll
    for (int o = 16; o; o >>= 1)
        c += __shfl_xor_sync(0xffffffffu, c, o);
    if (threadIdx.x == 0) out[0] = c;
}

// ------------------------------------------------------------------
extern "C" void kernel_launch(void* const* d_in, const int* in_sizes, int n_in,
                              void* d_out, int out_size)
{
    const float* trans      = (const float*)d_in[0];
    const float* pred       = (const float*)d_in[1];
    const int*   labels     = (const int*)  d_in[2];
    const int*   act_lens   = (const int*)  d_in[3];
    const int*   label_lens = (const int*)  d_in[4];
    float* out = (float*)d_out;

    k_prep<<<Bc * Tc + Bc * U1c, 128>>>(trans, pred, labels);
    k_joint<<<dim3(Tc / 4, Bc), 128>>>(trans, labels, label_lens);
    k_dp<<<Bc, 96>>>(act_lens, label_lens);
    k_final<<<1, 32>>>(out);
}

// round 3
// speedup vs baseline: 1.3323x; 1.3323x over previous
#include <cuda_runtime.h>
#include <cuda_bf16.h>

// Problem constants (fixed by the dataset): B=8, T=128, U=64, V=512
#define Bc  8
#define Tc  128
#define Uc  64
#define U1c 65
#define Vc  512
#define NEGV -1e30f

// ------------------------------------------------------------------
// Scratch (device globals; no allocation allowed)
// ------------------------------------------------------------------
__device__ float g_expT[Bc * Tc * Vc];    // exp(trans - rowmax)
__device__ float g_expP[Bc * U1c * Vc];   // exp(pred  - rowmax)
__device__ float g_Mt[Bc * Tc];
__device__ float g_tb0[Bc * Tc];          // trans[b,t,0]
__device__ float g_Mu[Bc * U1c];
__device__ float g_pb0[Bc * U1c];         // pred[b,u,0]
__device__ float g_plab[Bc * Uc];         // pred[b,u,labels[b,u]]
__device__ float g_logZ[Bc * Tc * U1c];   // log partition per lattice cell
__device__ float g_cost[Bc];
__device__ unsigned int g_ticket;         // zero-init; reset by last block

// ------------------------------------------------------------------
// K1: per-row max + exp(x - max), plus scalar gathers
// ------------------------------------------------------------------
__global__ void k_prep(const float* __restrict__ trans,
                       const float* __restrict__ pred,
                       const int*   __restrict__ labels)
{
    int blk = blockIdx.x;
    bool isT = (blk < Bc * Tc);
    int idx = isT ? blk : (blk - Bc * Tc);
    const float* row = isT ? (trans + (size_t)idx * Vc) : (pred + (size_t)idx * Vc);
    float*      erow = isT ? (g_expT + (size_t)idx * Vc) : (g_expP + (size_t)idx * Vc);

    int tid = threadIdx.x;                 // 128 threads, 4 floats each
    float4 v = ((const float4*)row)[tid];

    float m = fmaxf(fmaxf(v.x, v.y), fmaxf(v.z, v.w));
#pragma unroll
    for (int o = 16; o; o >>= 1)
        m = fmaxf(m, __shfl_xor_sync(0xffffffffu, m, o));

    __shared__ float sm[4];
    if ((tid & 31) == 0) sm[tid >> 5] = m;
    __syncthreads();
    m = fmaxf(fmaxf(sm[0], sm[1]), fmaxf(sm[2], sm[3]));

    float4 e;
    e.x = __expf(v.x - m);
    e.y = __expf(v.y - m);
    e.z = __expf(v.z - m);
    e.w = __expf(v.w - m);
    ((float4*)erow)[tid] = e;

    if (tid == 0) {
        if (isT) {
            g_Mt[idx]  = m;
            g_tb0[idx] = v.x;              // v.x of tid 0 == row[0]
        } else {
            g_Mu[idx]  = m;
            g_pb0[idx] = v.x;
            int b = idx / U1c, u = idx % U1c;
            if (u < Uc) {
                int l = labels[b * Uc + u];
                g_plab[b * Uc + u] = row[l];
            }
        }
    }
}

// ------------------------------------------------------------------
// K2: joint dots -> logZ only. Block = (b, 4 t-rows), 128 threads.
// No global loads inside the u loop except the prefetched expP row.
// ------------------------------------------------------------------
__global__ void k_joint()
{
    int b  = blockIdx.y;
    int t0 = blockIdx.x * 4;
    int tid = threadIdx.x, lane = tid & 31, w = tid >> 5;

    const float* eT = g_expT + ((size_t)(b * Tc + t0)) * Vc;
    float4 a0 = ((const float4*)(eT + 0 * Vc))[tid];
    float4 a1 = ((const float4*)(eT + 1 * Vc))[tid];
    float4 a2 = ((const float4*)(eT + 2 * Vc))[tid];
    float4 a3 = ((const float4*)(eT + 3 * Vc))[tid];

    __shared__ float part[2][4][4];        // [parity][warp][t-row]
    __shared__ float sMt[4];
    __shared__ float sMu[U1c];
    if (tid < 4) sMt[tid] = g_Mt[b * Tc + t0 + tid];
    if (tid < U1c) sMu[tid] = g_Mu[b * U1c + tid];
    __syncthreads();

    const float4* P = (const float4*)(g_expP + (size_t)b * U1c * Vc);
    float4 p = P[tid];                     // prefetch u = 0

    for (int u = 0; u < U1c; ++u) {
        float4 pc = p;
        if (u + 1 < U1c) p = P[(u + 1) * (Vc / 4) + tid];

        float s0 = a0.x * pc.x + a0.y * pc.y + a0.z * pc.z + a0.w * pc.w;
        float s1 = a1.x * pc.x + a1.y * pc.y + a1.z * pc.z + a1.w * pc.w;
        float s2 = a2.x * pc.x + a2.y * pc.y + a2.z * pc.z + a2.w * pc.w;
        float s3 = a3.x * pc.x + a3.y * pc.y + a3.z * pc.z + a3.w * pc.w;

#pragma unroll
        for (int o = 16; o; o >>= 1) {
            s0 += __shfl_xor_sync(0xffffffffu, s0, o);
            s1 += __shfl_xor_sync(0xffffffffu, s1, o);
            s2 += __shfl_xor_sync(0xffffffffu, s2, o);
            s3 += __shfl_xor_sync(0xffffffffu, s3, o);
        }
        int par = u & 1;
        if (lane == 0) {
            part[par][w][0] = s0;
            part[par][w][1] = s1;
            part[par][w][2] = s2;
            part[par][w][3] = s3;
        }
        __syncthreads();
        if (tid < 4) {
            float S = part[par][0][tid] + part[par][1][tid]
                    + part[par][2][tid] + part[par][3][tid];
            int t = t0 + tid;
            g_logZ[((size_t)(b * Tc + t)) * U1c + u]
                = sMt[tid] + sMu[u] + __logf(S);
        }
    }
}

// ------------------------------------------------------------------
// K3: fused table build + alpha DP wavefront + final reduction.
// One block per batch element, 96 threads (thread u owns column u).
// BL/LB tables live entirely in dynamic shared memory.
// ------------------------------------------------------------------
__global__ void k_dp(const float* __restrict__ trans,
                     const int*   __restrict__ labels,
                     const int*   __restrict__ act_lens,
                     const int*   __restrict__ label_lens,
                     float*       __restrict__ out)
{
    extern __shared__ float smem[];
    float* sBL = smem;                     // [Tc][U1c]
    float* sLB = smem + Tc * U1c;          // [Tc][Uc]
    float* diag = sLB + Tc * Uc;           // [2][U1c]
    __shared__ float sCost;

    int b = blockIdx.x;
    int tid = threadIdx.x;
    int tlen = act_lens[b];
    int ulen = label_lens[b];

    // ---- prologue: build BL / LB tables (fully parallel, MLP-hidden) ----
    const float* LZ = g_logZ + (size_t)b * Tc * U1c;
    const float* tb0 = g_tb0 + b * Tc;
    const float* pb0 = g_pb0 + b * U1c;
    const float* plab = g_plab + b * Uc;
    const int*   lab  = labels + b * Uc;

    for (int i = tid; i < Tc * U1c; i += 96) {
        int t = i / U1c, u = i - t * U1c;
        float lz = LZ[i];
        sBL[i] = tb0[t] + pb0[u] - lz;
        if (u < Uc) {
            float lv = NEGV;
            if (u < ulen) {
                int l = lab[u];
                lv = trans[((size_t)(b * Tc + t)) * Vc + l] + plab[u] - lz;
            }
            sLB[t * Uc + u] = lv;
        }
    }
    __syncthreads();

    // ---- wavefront DP over anti-diagonals ----
    int u = tid;
    float myPrev = 0.0f;

    for (int s = 0; s <= (Tc - 1) + Uc; ++s) {
        int cur = s & 1, prv = cur ^ 1;
        bool active = (u <= Uc) && (u <= s) && ((s - u) <= Tc - 1);
        if (active) {
            int t = s - u;
            float val;
            if (t == 0) {
                val = (u == 0) ? 0.0f
                               : diag[prv * U1c + (u - 1)] + sLB[u - 1];
            } else if (u == 0) {
                val = myPrev + sBL[(t - 1) * U1c];
            } else {
                float A  = myPrev + sBL[(t - 1) * U1c + u];
                float Bv = diag[prv * U1c + (u - 1)] + sLB[t * Uc + (u - 1)];
                float m  = fmaxf(A, Bv);
                val = m + __logf(1.0f + __expf(-fabsf(A - Bv)));
            }
            diag[cur * U1c + u] = val;
            myPrev = val;
            if (t == tlen - 1 && u == ulen)
                sCost = -(val + sBL[t * U1c + u]);
        }
        __syncthreads();
    }

    // ---- fused finalize: last block to finish sums all costs ----
    if (tid == 0) {
        g_cost[b] = sCost;
        __threadfence();
        unsigned int old = atomicAdd(&g_ticket, 1u);
        if (old == Bc - 1) {
            float s = 0.0f;
#pragma unroll
            for (int i = 0; i < Bc; ++i) s += g_cost[i];
            out[0] = s;
            atomicExch(&g_ticket, 0u);     // reset for next graph replay
        }
    }
}

// ------------------------------------------------------------------
extern "C" void kernel_launch(void* const* d_in, const int* in_sizes, int n_in,
                              void* d_out, int out_size)
{
    const float* trans      = (const float*)d_in[0];
    const float* pred       = (const float*)d_in[1];
    const int*   labels     = (const int*)  d_in[2];
    const int*   act_lens   = (const int*)  d_in[3];
    const int*   label_lens = (const int*)  d_in[4];
    float* out = (float*)d_out;

    const int dpSmem = (Tc * U1c + Tc * Uc + 2 * U1c) * sizeof(float); // ~66.6 KB
    cudaFuncSetAttribute(k_dp, cudaFuncAttributeMaxDynamicSharedMemorySize, dpSmem);

    k_prep<<<Bc * Tc + Bc * U1c, 128>>>(trans, pred, labels);
    k_joint<<<dim3(Tc / 4, Bc), 128>>>();
    k_dp<<<Bc, 96, dpSmem>>>(trans, labels, act_lens, label_lens, out);
}

// round 4
// speedup vs baseline: 2.5080x; 1.8825x over previous
#include <cuda_runtime.h>
#include <cuda_bf16.h>

// Problem constants (fixed): B=8, T=128, U=64, V=512
#define Bc  8
#define Tc  128
#define Uc  64
#define U1c 65
#define Vc  512
#define NEGV  -1e30f
#define LOG2E 1.4426950408889634f
#define LN2F  0.6931471805599453f

// ------------------------------------------------------------------
// Scratch (device globals)
// ------------------------------------------------------------------
__device__ __align__(16) float g_expP[Bc * U1c * Vc];
__device__ float g_Mu[Bc * U1c];
__device__ float g_pb0[Bc * U1c];
__device__ float g_plab[Bc * Uc];
__device__ __align__(16) float g_BL[Bc * Tc * U1c];  // blank log-prob, LOG2 domain
__device__ __align__(16) float g_LB[Bc * Tc * Uc];   // label log-prob, LOG2 domain
__device__ float g_cost[Bc];
__device__ unsigned int g_bcnt[Bc];   // zero-init; reset each run
__device__ unsigned int g_ticket;     // zero-init; reset each run

__device__ __forceinline__ float laddexp2(float x, float y)
{
    float m = fmaxf(x, y);
    float d = fabsf(x - y);
    return m + __log2f(1.0f + exp2f(-d));
}

// ------------------------------------------------------------------
// K1: pred rows only: rowmax + exp(x-max), Mu/pb0/plab gathers
// ------------------------------------------------------------------
__global__ void k_prep_pred(const float* __restrict__ pred,
                            const int*   __restrict__ labels)
{
    int idx = blockIdx.x;                  // [0, Bc*U1c)
    const float* row = pred + (size_t)idx * Vc;
    float* erow = g_expP + (size_t)idx * Vc;

    int tid = threadIdx.x;                 // 128 threads, 4 floats each
    float4 v = ((const float4*)row)[tid];

    float m = fmaxf(fmaxf(v.x, v.y), fmaxf(v.z, v.w));
#pragma unroll
    for (int o = 16; o; o >>= 1)
        m = fmaxf(m, __shfl_xor_sync(0xffffffffu, m, o));

    __shared__ float sm[4];
    if ((tid & 31) == 0) sm[tid >> 5] = m;
    __syncthreads();
    m = fmaxf(fmaxf(sm[0], sm[1]), fmaxf(sm[2], sm[3]));

    float4 e;
    e.x = __expf(v.x - m);
    e.y = __expf(v.y - m);
    e.z = __expf(v.z - m);
    e.w = __expf(v.w - m);
    ((float4*)erow)[tid] = e;

    if (tid == 0) {
        g_Mu[idx]  = m;
        g_pb0[idx] = v.x;                  // row[0]
        int b = idx / U1c, u = idx % U1c;
        if (u < Uc) {
            int l = labels[b * Uc + u];
            g_plab[b * Uc + u] = row[l];
        }
    }
}

// ------------------------------------------------------------------
// K2 (fused): joint + chained DP.
// Grid (Tc/4, Bc), 256 threads.
//  Phase A: block computes exp of its 4 trans rows into dyn smem.
//  Phase B: each warp privately owns 8 u-columns -> BL/LB (no barriers).
//  Phase C: the LAST block of batch b runs the full alpha DP for b
//           (single-warp systolic, zero barriers) + final batch sum.
// ------------------------------------------------------------------
__global__ void __launch_bounds__(256)
k_main(const float* __restrict__ trans,
       const int*   __restrict__ labels,
       const int*   __restrict__ act_lens,
       const int*   __restrict__ label_lens,
       float*       __restrict__ out)
{
    extern __shared__ float dsmem[];       // phase A/B: sexp[4*512]; phase C: sBL/sLB
    __shared__ float sMu[U1c], spb0[U1c], splab[Uc];
    __shared__ int   slab[Uc];
    __shared__ float wmax[8], sMt[4], stb0[4];
    __shared__ int   sUlen, sLast;

    int b   = blockIdx.y;
    int t0  = blockIdx.x * 4;
    int tid = threadIdx.x;
    int lane = tid & 31, w = tid >> 5;

    // ---------------- Phase A: trans rows -> exp in smem ----------------
    int r = tid >> 6;                      // t-row 0..3
    int j = tid & 63;                      // 8 elems each
    const float* trow = trans + ((size_t)(b * Tc + t0 + r)) * Vc;
    float4 v0 = ((const float4*)trow)[2 * j];
    float4 v1 = ((const float4*)trow)[2 * j + 1];

    float m = fmaxf(fmaxf(fmaxf(v0.x, v0.y), fmaxf(v0.z, v0.w)),
                    fmaxf(fmaxf(v1.x, v1.y), fmaxf(v1.z, v1.w)));
#pragma unroll
    for (int o = 16; o; o >>= 1)
        m = fmaxf(m, __shfl_xor_sync(0xffffffffu, m, o));
    if (lane == 0) wmax[w] = m;

    // per-b small arrays (independent of wmax sync)
    if (tid < U1c) { sMu[tid] = g_Mu[b * U1c + tid]; spb0[tid] = g_pb0[b * U1c + tid]; }
    if (tid < Uc)  { splab[tid] = g_plab[b * Uc + tid]; slab[tid] = labels[b * Uc + tid]; }
    if (tid == 0)  sUlen = label_lens[b];
    __syncthreads();

    m = fmaxf(wmax[2 * r], wmax[2 * r + 1]);
    float4 e0, e1;
    e0.x = __expf(v0.x - m); e0.y = __expf(v0.y - m);
    e0.z = __expf(v0.z - m); e0.w = __expf(v0.w - m);
    e1.x = __expf(v1.x - m); e1.y = __expf(v1.y - m);
    e1.z = __expf(v1.z - m); e1.w = __expf(v1.w - m);
    ((float4*)dsmem)[r * 128 + 2 * j]     = e0;
    ((float4*)dsmem)[r * 128 + 2 * j + 1] = e1;
    if (j == 0) { sMt[r] = m; stb0[r] = v0.x; }
    __syncthreads();

    // ---------------- Phase B: warp-private u columns ----------------
    // a regs: 4 rows x 16 floats (element 4*(lane+32k)+m)
    float4 a[16];
#pragma unroll
    for (int jr = 0; jr < 4; ++jr)
#pragma unroll
        for (int k = 0; k < 4; ++k)
            a[jr * 4 + k] = ((const float4*)dsmem)[jr * 128 + lane + 32 * k];

    const float4* P = (const float4*)(g_expP + (size_t)b * U1c * Vc);
    int nu = (w == 0) ? 9 : 8;             // warp0 also covers u=64
    int u  = w;
    float4 p0 = P[u * 128 + lane],       p1 = P[u * 128 + lane + 32],
           p2 = P[u * 128 + lane + 64],  p3 = P[u * 128 + lane + 96];

    for (int i = 0; i < nu; ++i) {
        float4 q0 = p0, q1 = p1, q2 = p2, q3 = p3;
        int un = u + 8;
        if (i + 1 < nu) {
            p0 = P[un * 128 + lane];      p1 = P[un * 128 + lane + 32];
            p2 = P[un * 128 + lane + 64]; p3 = P[un * 128 + lane + 96];
        }

        float s0, s1, s2, s3;
        {
            s0 = a[0].x*q0.x + a[0].y*q0.y + a[0].z*q0.z + a[0].w*q0.w
               + a[1].x*q1.x + a[1].y*q1.y + a[1].z*q1.z + a[1].w*q1.w
               + a[2].x*q2.x + a[2].y*q2.y + a[2].z*q2.z + a[2].w*q2.w
               + a[3].x*q3.x + a[3].y*q3.y + a[3].z*q3.z + a[3].w*q3.w;
            s1 = a[4].x*q0.x + a[4].y*q0.y + a[4].z*q0.z + a[4].w*q0.w
               + a[5].x*q1.x + a[5].y*q1.y + a[5].z*q1.z + a[5].w*q1.w
               + a[6].x*q2.x + a[6].y*q2.y + a[6].z*q2.z + a[6].w*q2.w
               + a[7].x*q3.x + a[7].y*q3.y + a[7].z*q3.z + a[7].w*q3.w;
            s2 = a[8].x*q0.x + a[8].y*q0.y + a[8].z*q0.z + a[8].w*q0.w
               + a[9].x*q1.x + a[9].y*q1.y + a[9].z*q1.z + a[9].w*q1.w
               + a[10].x*q2.x + a[10].y*q2.y + a[10].z*q2.z + a[10].w*q2.w
               + a[11].x*q3.x + a[11].y*q3.y + a[11].z*q3.z + a[11].w*q3.w;
            s3 = a[12].x*q0.x + a[12].y*q0.y + a[12].z*q0.z + a[12].w*q0.w
               + a[13].x*q1.x + a[13].y*q1.y + a[13].z*q1.z + a[13].w*q1.w
               + a[14].x*q2.x + a[14].y*q2.y + a[14].z*q2.z + a[14].w*q2.w
               + a[15].x*q3.x + a[15].y*q3.y + a[15].z*q3.z + a[15].w*q3.w;
        }
#pragma unroll
        for (int o = 16; o; o >>= 1) {
            s0 += __shfl_xor_sync(0xffffffffu, s0, o);
            s1 += __shfl_xor_sync(0xffffffffu, s1, o);
            s2 += __shfl_xor_sync(0xffffffffu, s2, o);
            s3 += __shfl_xor_sync(0xffffffffu, s3, o);
        }
        if (lane < 4) {
            float S = (lane == 0) ? s0 : (lane == 1) ? s1 : (lane == 2) ? s2 : s3;
            int t = t0 + lane;
            float logZ = sMt[lane] + sMu[u] + __logf(S);
            g_BL[((size_t)(b * Tc + t)) * U1c + u]
                = (stb0[lane] + spb0[u] - logZ) * LOG2E;
            if (u < Uc) {
                float lv = NEGV;
                if (u < sUlen) {
                    int l = slab[u];
                    float traw = __logf(dsmem[lane * Vc + l]) + sMt[lane];
                    lv = (traw + splab[u] - logZ) * LOG2E;
                }
                g_LB[((size_t)(b * Tc + t)) * Uc + u] = lv;
            }
        }
        u = un;
    }

    // ---------------- Phase C: last block of batch b runs the DP ----------------
    __threadfence();
    __syncthreads();
    if (tid == 0) {
        unsigned int old = atomicAdd(&g_bcnt[b], 1u);
        sLast = (old == 31u);
    }
    __syncthreads();
    if (!sLast) return;
    if (tid == 0) atomicExch(&g_bcnt[b], 0u);  // reset for next graph replay
    __threadfence();                            // acquire other blocks' BL/LB

    float* sBL = dsmem;                         // [Tc][U1c], log2 domain
    float* sLB = dsmem + Tc * U1c;              // [Tc][Uc],  log2 domain
    {
        const float4* BLg = (const float4*)(g_BL + (size_t)b * Tc * U1c);
        const float4* LBg = (const float4*)(g_LB + (size_t)b * Tc * Uc);
        for (int i = tid; i < (Tc * U1c) / 4; i += 256) ((float4*)sBL)[i] = BLg[i];
        for (int i = tid; i < (Tc * Uc) / 4;  i += 256) ((float4*)sLB)[i] = LBg[i];
    }
    __syncthreads();
    if (tid >= 32) return;

    int L = tid;                                // lane owns u = {2L, 2L+1}; L==31 also u=64
    int tlen = act_lens[b];
    int ulen = label_lens[b];
    float vA = 0.0f, vB = 0.0f, vC = 0.0f;
    float cost = 0.0f;
    bool  have = false;
    int   uA = 2 * L, uB = 2 * L + 1;

    for (int k = 0; k < Tc + 32; ++k) {
        float leftPrev = __shfl_up_sync(0xffffffffu, vB, 1); // lane L-1's u=2L-1 at our t
        int t = k - L;
        if (t >= 0 && t < Tc) {
            float nA, nB;
            if (t == 0) {
                nA = (L == 0) ? 0.0f : leftPrev + sLB[uA - 1];
                nB = nA + sLB[uB - 1];
            } else {
                float below = vA + sBL[(t - 1) * U1c + uA];
                nA = (L == 0) ? below
                              : laddexp2(below, leftPrev + sLB[t * Uc + uA - 1]);
                nB = laddexp2(vB + sBL[(t - 1) * U1c + uB],
                              nA + sLB[t * Uc + uB - 1]);
            }
            vA = nA; vB = nB;
            if (L == 31) {
                float nC = (t == 0) ? (nB + sLB[63])
                                    : laddexp2(vC + sBL[(t - 1) * U1c + 64],
                                               nB + sLB[t * Uc + 63]);
                vC = nC;
            }
            if (t == tlen - 1) {
                if (ulen == uA)                  { cost = vA + sBL[t * U1c + uA]; have = true; }
                else if (ulen == uB)             { cost = vB + sBL[t * U1c + uB]; have = true; }
                else if (L == 31 && ulen == 64)  { cost = vC + sBL[t * U1c + 64]; have = true; }
            }
        }
    }

    if (have) {
        g_cost[b] = -cost * LN2F;
        __threadfence();
        unsigned int old = atomicAdd(&g_ticket, 1u);
        if (old == Bc - 1) {
            __threadfence();
            float s = 0.0f;
#pragma unroll
            for (int i = 0; i < Bc; ++i) s += g_cost[i];
            out[0] = s;
            atomicExch(&g_ticket, 0u);          // reset for next graph replay
        }
    }
}

// ------------------------------------------------------------------
extern "C" void kernel_launch(void* const* d_in, const int* in_sizes, int n_in,
                              void* d_out, int out_size)
{
    const float* trans      = (const float*)d_in[0];
    const float* pred       = (const float*)d_in[1];
    const int*   labels     = (const int*)  d_in[2];
    const int*   act_lens   = (const int*)  d_in[3];
    const int*   label_lens = (const int*)  d_in[4];
    float* out = (float*)d_out;

    const int dynSmem = (Tc * U1c + Tc * Uc) * sizeof(float); // 66048 B
    cudaFuncSetAttribute(k_main, cudaFuncAttributeMaxDynamicSharedMemorySize, dynSmem);

    k_prep_pred<<<Bc * U1c, 128>>>(pred, labels);
    k_main<<<dim3(Tc / 4, Bc), 256, dynSmem>>>(trans, labels, act_lens, label_lens, out);
}